// round 1
// baseline (speedup 1.0000x reference)
#include <cuda_runtime.h>

// Horizontal correlation cost volume.
// a,b: fp32 [B=8, C=128, H=192, W=256], D=40.
// out[b, ctr, h, w] = sum_c a[b,c,h,w] * bp[b,c,h, ctr+w],  bp = b left-padded by 40.
//
// One CTA per (batch, h) row. 192 threads = 6 warps.
// warp = ctr-tile (CT=8 ctrs), lane = w-tile (WT=8 w's). 64 fp32 accumulators/thread.
// Channels streamed through smem in chunks of CC=16.
//
// smem rows are stored in a parity-permuted float4 layout:
//   perm(block) = (block>>1) + (block&1)*NBLK_HALF
// so that all compute-side LDS.128 (lane-stride of 2 original blocks = 1 permuted
// block = 16B) are bank-conflict-free. The loader writes through the inverse
// permutation, so STS.128 is also conflict-free.

#define CC      16
#define C_TOT   128
#define NCHUNK  (C_TOT / CC)
#define W_DIM   256
#define H_DIM   192
#define B_DIM   8
#define D_MAX   40
#define NCTR    (D_MAX + 1)       // 41
#define ABLK    64                // a row: 256 floats = 64 float4 blocks
#define BBLK    76                // bp row: 304 floats (40 zero | 256 data | 8 zero)
#define NT      192

__global__ __launch_bounds__(NT, 3)
void corr_kernel(const float* __restrict__ A,
                 const float* __restrict__ B,
                 float* __restrict__ O)
{
    __shared__ float4 a_s[CC][ABLK];   // 16 KB
    __shared__ float4 b_s[CC][BBLK];   // 19 KB

    const int row  = blockIdx.x;           // 0 .. B*H-1
    const int bi   = row / H_DIM;
    const int h    = row - bi * H_DIM;
    const int tid  = threadIdx.x;
    const int warp = tid >> 5;              // ctr-tile: ctr in [8*warp, 8*warp+8)
    const int lane = tid & 31;              // w-tile:   w   in [8*lane, 8*lane+8)

    const size_t plane = (size_t)H_DIM * W_DIM;     // stride between channels
    const float* Arow = A + ((size_t)bi * C_TOT * H_DIM + h) * W_DIM;
    const float* Brow = B + ((size_t)bi * C_TOT * H_DIM + h) * W_DIM;

    float acc[8][8];
#pragma unroll
    for (int i = 0; i < 8; ++i)
#pragma unroll
        for (int j = 0; j < 8; ++j)
            acc[i][j] = 0.0f;

    for (int ch = 0; ch < NCHUNK; ++ch) {
        __syncthreads();   // protect smem from previous iteration's readers

        // ---- load a chunk: CC rows x 64 blocks, inverse-permuted store ----
#pragma unroll 1
        for (int idx = tid; idx < CC * ABLK; idx += NT) {
            int c = idx >> 6;
            int p = idx & 63;
            int g = (p < 32) ? (2 * p) : (2 * (p - 32) + 1);   // original block
            const float4* src =
                (const float4*)(Arow + (size_t)(ch * CC + c) * plane);
            a_s[c][p] = src[g];
        }
        // ---- load bp chunk: CC rows x 76 blocks (zero pad handled inline) ----
#pragma unroll 1
        for (int idx = tid; idx < CC * BBLK; idx += NT) {
            int c = idx / BBLK;
            int p = idx - c * BBLK;
            int blk = (p < 38) ? (2 * p) : (2 * (p - 38) + 1); // original block
            int g = blk - 10;                                   // data starts at block 10
            float4 v = make_float4(0.f, 0.f, 0.f, 0.f);
            if (g >= 0 && g < 64) {
                const float4* src =
                    (const float4*)(Brow + (size_t)(ch * CC + c) * plane);
                v = src[g];
            }
            b_s[c][p] = v;
        }
        __syncthreads();

        // ---- compute: 16 channels x 64 FMA, 6 conflict-free LDS.128 per c ----
#pragma unroll
        for (int c = 0; c < CC; ++c) {
            // a blocks 2*lane, 2*lane+1  -> perm positions lane, 32+lane
            float4 a0 = a_s[c][lane];
            float4 a1 = a_s[c][32 + lane];
            // bp window base float = 8*warp + 8*lane -> blocks 2*(warp+lane)+k
            // perm positions: warp+lane, 38+warp+lane, warp+lane+1, 39+warp+lane
            float4 b0 = b_s[c][warp + lane];
            float4 b1 = b_s[c][38 + warp + lane];
            float4 b2 = b_s[c][warp + lane + 1];
            float4 b3 = b_s[c][39 + warp + lane];

            float av[8] = {a0.x, a0.y, a0.z, a0.w, a1.x, a1.y, a1.z, a1.w};
            float bw[16] = {b0.x, b0.y, b0.z, b0.w,
                            b1.x, b1.y, b1.z, b1.w,
                            b2.x, b2.y, b2.z, b2.w,
                            b3.x, b3.y, b3.z, b3.w};
#pragma unroll
            for (int i = 0; i < 8; ++i)
#pragma unroll
                for (int j = 0; j < 8; ++j)
                    acc[i][j] = fmaf(av[j], bw[i + j], acc[i][j]);
        }
    }

    // ---- store: 2 float4 per valid ctr, fully coalesced across lanes ----
    const int w0 = lane * 8;
#pragma unroll
    for (int i = 0; i < 8; ++i) {
        int ctr = warp * 8 + i;
        if (ctr < NCTR) {
            float* dst = O + (((size_t)bi * NCTR + ctr) * H_DIM + h) * W_DIM + w0;
            float4 v0 = make_float4(acc[i][0], acc[i][1], acc[i][2], acc[i][3]);
            float4 v1 = make_float4(acc[i][4], acc[i][5], acc[i][6], acc[i][7]);
            ((float4*)dst)[0] = v0;
            ((float4*)dst)[1] = v1;
        }
    }
}

extern "C" void kernel_launch(void* const* d_in, const int* in_sizes, int n_in,
                              void* d_out, int out_size)
{
    const float* a = (const float*)d_in[0];
    const float* b = (const float*)d_in[1];
    // d_in[2] = max_displacement (fixed at 40 for this problem's shapes)
    float* out = (float*)d_out;

    dim3 grid(B_DIM * H_DIM);   // 1536 CTAs, one per (batch, h) row
    dim3 block(NT);
    corr_kernel<<<grid, block>>>(a, b, out);
}

// round 2
// speedup vs baseline: 1.4685x; 1.4685x over previous
#include <cuda_runtime.h>
#include <cstdint>

// Horizontal correlation cost volume, cp.async double-buffered.
// a,b: fp32 [B=8, C=128, H=192, W=256], D=40.
// out[b, ctr, h, w] = sum_c a[b,c,h,w] * bp[b,c,h, ctr+w],  bp = b left-padded by 40.
//
// One CTA per (batch, h) row. 192 threads = 6 warps.
// warp = ctr-tile (8 ctrs), lane = w-tile (8 w's). 64 fp32 accumulators/thread.
// Channels streamed in chunks of CC=8 through a 2-stage cp.async smem pipeline.
//
// smem rows use a parity-permuted float4 layout so compute-side LDS.128
// (lane-stride 16B) is bank-conflict-free:
//   perm(block) = (block>>1) + (block&1)*NBLK_HALF

#define CC      8
#define C_TOT   128
#define NCHUNK  (C_TOT / CC)      // 16
#define W_DIM   256
#define H_DIM   192
#define B_DIM   8
#define D_MAX   40
#define NCTR    (D_MAX + 1)       // 41
#define ABLK    64                // a row: 256 floats = 64 float4 blocks
#define BBLK    76                // bp row: 304 floats (40 zero | 256 data | 8 zero)
#define NT      192

__device__ __forceinline__ void cpasync16(uint32_t dst, const void* src) {
    asm volatile("cp.async.cg.shared.global [%0], [%1], 16;\n" :: "r"(dst), "l"(src));
}
__device__ __forceinline__ void cp_commit() {
    asm volatile("cp.async.commit_group;\n");
}
__device__ __forceinline__ void cp_wait0() {
    asm volatile("cp.async.wait_group 0;\n" ::: "memory");
}

__global__ __launch_bounds__(NT, 3)
void corr_kernel(const float* __restrict__ A,
                 const float* __restrict__ B,
                 float* __restrict__ O)
{
    __shared__ float4 a_s[2][CC][ABLK];   // 16 KB
    __shared__ float4 b_s[2][CC][BBLK];   // 19 KB

    const int row  = blockIdx.x;            // 0 .. B*H-1
    const int bi   = row / H_DIM;
    const int h    = row - bi * H_DIM;
    const int tid  = threadIdx.x;
    const int warp = tid >> 5;               // ctr-tile
    const int lane = tid & 31;               // w-tile

    const size_t plane = (size_t)H_DIM * W_DIM;
    const float* Arow = A + ((size_t)bi * C_TOT * H_DIM + h) * W_DIM;
    const float* Brow = B + ((size_t)bi * C_TOT * H_DIM + h) * W_DIM;

    const uint32_t a_base = (uint32_t)__cvta_generic_to_shared(&a_s[0][0][0]);
    const uint32_t b_base = (uint32_t)__cvta_generic_to_shared(&b_s[0][0][0]);

    // ---- zero the 12 permanent pad blocks of each b buffer/channel, once ----
    // pad permuted positions: {0,1,2,3,4, 37, 38,39,40,41,42, 75}
    {
        int t = tid;                      // 2 bufs * CC * 12 = 192 = NT exactly
        int buf = t / (CC * 12);
        int r   = t - buf * (CC * 12);
        int c   = r / 12;
        int j   = r - c * 12;
        int p   = (j < 5) ? j : ((j < 11) ? (32 + j) : 75);
        b_s[buf][c][p] = make_float4(0.f, 0.f, 0.f, 0.f);
    }

    float acc[8][8];
#pragma unroll
    for (int i = 0; i < 8; ++i)
#pragma unroll
        for (int j = 0; j < 8; ++j)
            acc[i][j] = 0.0f;

    // ---- prefetch helper (issued for chunk ch into buffer buf) ----
    auto prefetch = [&](int ch, int buf) {
        const float* Ab = Arow + (size_t)ch * CC * plane;
        const float* Bb = Brow + (size_t)ch * CC * plane;
#pragma unroll 1
        for (int idx = tid; idx < CC * 64; idx += NT) {
            int c = idx >> 6, p = idx & 63;
            int g = (p < 32) ? (2 * p) : (2 * (p - 32) + 1);
            uint32_t dst = a_base + ((((buf * CC + c) * ABLK) + p) << 4);
            cpasync16(dst, Ab + (size_t)c * plane + g * 4);
        }
#pragma unroll 1
        for (int idx = tid; idx < CC * 64; idx += NT) {
            int c = idx >> 6, g = idx & 63;
            int blk = g + 10;                                   // bp block index
            int p = (blk & 1) ? (38 + (blk >> 1)) : (blk >> 1); // permuted pos
            uint32_t dst = b_base + ((((buf * CC + c) * BBLK) + p) << 4);
            cpasync16(dst, Bb + (size_t)c * plane + g * 4);
        }
        cp_commit();
    };

    prefetch(0, 0);

    for (int ch = 0; ch < NCHUNK; ++ch) {
        const int buf = ch & 1;
        cp_wait0();            // chunk ch resident (this thread's copies)
        __syncthreads();       // all threads' copies visible; prev compute done

        if (ch + 1 < NCHUNK)
            prefetch(ch + 1, buf ^ 1);   // overlaps with compute below

        // ---- compute: CC channels x 64 FMA, 6 conflict-free LDS.128 per c ----
#pragma unroll
        for (int c = 0; c < CC; ++c) {
            float4 a0 = a_s[buf][c][lane];
            float4 a1 = a_s[buf][c][32 + lane];
            float4 b0 = b_s[buf][c][warp + lane];
            float4 b1 = b_s[buf][c][38 + warp + lane];
            float4 b2 = b_s[buf][c][warp + lane + 1];
            float4 b3 = b_s[buf][c][39 + warp + lane];

            float av[8] = {a0.x, a0.y, a0.z, a0.w, a1.x, a1.y, a1.z, a1.w};
            float bw[16] = {b0.x, b0.y, b0.z, b0.w,
                            b1.x, b1.y, b1.z, b1.w,
                            b2.x, b2.y, b2.z, b2.w,
                            b3.x, b3.y, b3.z, b3.w};
#pragma unroll
            for (int i = 0; i < 8; ++i)
#pragma unroll
                for (int j = 0; j < 8; ++j)
                    acc[i][j] = fmaf(av[j], bw[i + j], acc[i][j]);
        }
    }

    // ---- store: 2 float4 per valid ctr, fully coalesced across lanes ----
    const int w0 = lane * 8;
#pragma unroll
    for (int i = 0; i < 8; ++i) {
        int ctr = warp * 8 + i;
        if (ctr < NCTR) {
            float* dst = O + (((size_t)bi * NCTR + ctr) * H_DIM + h) * W_DIM + w0;
            ((float4*)dst)[0] = make_float4(acc[i][0], acc[i][1], acc[i][2], acc[i][3]);
            ((float4*)dst)[1] = make_float4(acc[i][4], acc[i][5], acc[i][6], acc[i][7]);
        }
    }
}

extern "C" void kernel_launch(void* const* d_in, const int* in_sizes, int n_in,
                              void* d_out, int out_size)
{
    const float* a = (const float*)d_in[0];
    const float* b = (const float*)d_in[1];
    float* out = (float*)d_out;

    dim3 grid(B_DIM * H_DIM);   // 1536 CTAs, one per (batch, h) row
    dim3 block(NT);
    corr_kernel<<<grid, block>>>(a, b, out);
}

// round 3
// speedup vs baseline: 1.4839x; 1.0105x over previous
#include <cuda_runtime.h>
#include <cstdint>

// Horizontal correlation cost volume, cp.async double-buffered + f32x2 FMA.
// a,b: fp32 [B=8, C=128, H=192, W=256], D=40.
// out[b, ctr, h, w] = sum_c a[b,c,h,w] * bp[b,c,h, ctr+w],  bp = b left-padded by 40.
//
// One CTA per (batch, h) row. 192 threads = 6 warps.
// warp = ctr-tile (8 ctrs), lane = w-tile (8 w's). 64 fp32 accs/thread packed as
// 32 f32x2 pairs -> fma.rn.f32x2 halves FMA issue slots vs scalar FFMA.
//
// smem rows use a parity-permuted float4 layout so compute-side LDS.128
// (lane-stride 16B) is bank-conflict-free.

#define CC      8
#define C_TOT   128
#define NCHUNK  (C_TOT / CC)      // 16
#define W_DIM   256
#define H_DIM   192
#define B_DIM   8
#define D_MAX   40
#define NCTR    (D_MAX + 1)       // 41
#define ABLK    64
#define BBLK    76
#define NT      192

typedef unsigned long long ull;

__device__ __forceinline__ void cpasync16(uint32_t dst, const void* src) {
    asm volatile("cp.async.cg.shared.global [%0], [%1], 16;\n" :: "r"(dst), "l"(src));
}
__device__ __forceinline__ void cp_commit() {
    asm volatile("cp.async.commit_group;\n");
}
__device__ __forceinline__ void cp_wait0() {
    asm volatile("cp.async.wait_group 0;\n" ::: "memory");
}
__device__ __forceinline__ ull pack2(float lo, float hi) {
    ull r;
    asm("mov.b64 %0, {%1, %2};" : "=l"(r) : "f"(lo), "f"(hi));
    return r;
}
__device__ __forceinline__ void fma2(ull& d, ull a, ull b) {
    asm("fma.rn.f32x2 %0, %1, %2, %0;" : "+l"(d) : "l"(a), "l"(b));
}
__device__ __forceinline__ void unpack2(ull v, float& lo, float& hi) {
    asm("mov.b64 {%0, %1}, %2;" : "=f"(lo), "=f"(hi) : "l"(v));
}

__global__ __launch_bounds__(NT, 3)
void corr_kernel(const float* __restrict__ A,
                 const float* __restrict__ B,
                 float* __restrict__ O)
{
    __shared__ float4 a_s[2][CC][ABLK];   // 16 KB
    __shared__ float4 b_s[2][CC][BBLK];   // 19 KB

    const int row  = blockIdx.x;
    const int bi   = row / H_DIM;
    const int h    = row - bi * H_DIM;
    const int tid  = threadIdx.x;
    const int warp = tid >> 5;
    const int lane = tid & 31;

    const size_t plane = (size_t)H_DIM * W_DIM;
    const float* Arow = A + ((size_t)bi * C_TOT * H_DIM + h) * W_DIM;
    const float* Brow = B + ((size_t)bi * C_TOT * H_DIM + h) * W_DIM;

    const uint32_t a_base = (uint32_t)__cvta_generic_to_shared(&a_s[0][0][0]);
    const uint32_t b_base = (uint32_t)__cvta_generic_to_shared(&b_s[0][0][0]);

    // zero the 12 permanent pad blocks of each b buffer/channel (never reloaded)
    {
        int t = tid;                      // 2 bufs * CC * 12 = 192 = NT exactly
        int buf = t / (CC * 12);
        int r   = t - buf * (CC * 12);
        int c   = r / 12;
        int j   = r - c * 12;
        int p   = (j < 5) ? j : ((j < 11) ? (32 + j) : 75);
        b_s[buf][c][p] = make_float4(0.f, 0.f, 0.f, 0.f);
    }

    // acc2[i][jp] = (acc[i][2jp], acc[i][2jp+1]) : ctr = 8*warp+i, w = 8*lane+2jp
    ull acc2[8][4];
#pragma unroll
    for (int i = 0; i < 8; ++i)
#pragma unroll
        for (int jp = 0; jp < 4; ++jp)
            acc2[i][jp] = 0ull;

    auto prefetch = [&](int ch, int buf) {
        const float* Ab = Arow + (size_t)ch * CC * plane;
        const float* Bb = Brow + (size_t)ch * CC * plane;
#pragma unroll 1
        for (int idx = tid; idx < CC * 64; idx += NT) {
            int c = idx >> 6, p = idx & 63;
            int g = (p < 32) ? (2 * p) : (2 * (p - 32) + 1);
            uint32_t dst = a_base + ((((buf * CC + c) * ABLK) + p) << 4);
            cpasync16(dst, Ab + (size_t)c * plane + g * 4);
        }
#pragma unroll 1
        for (int idx = tid; idx < CC * 64; idx += NT) {
            int c = idx >> 6, g = idx & 63;
            int blk = g + 10;
            int p = (blk & 1) ? (38 + (blk >> 1)) : (blk >> 1);
            uint32_t dst = b_base + ((((buf * CC + c) * BBLK) + p) << 4);
            cpasync16(dst, Bb + (size_t)c * plane + g * 4);
        }
        cp_commit();
    };

    prefetch(0, 0);

    for (int ch = 0; ch < NCHUNK; ++ch) {
        const int buf = ch & 1;
        cp_wait0();
        __syncthreads();

        if (ch + 1 < NCHUNK)
            prefetch(ch + 1, buf ^ 1);   // overlaps with compute below

#pragma unroll
        for (int c = 0; c < CC; ++c) {
            float4 a0 = a_s[buf][c][lane];
            float4 a1 = a_s[buf][c][32 + lane];
            float4 b0 = b_s[buf][c][warp + lane];
            float4 b1 = b_s[buf][c][38 + warp + lane];
            float4 b2 = b_s[buf][c][warp + lane + 1];
            float4 b3 = b_s[buf][c][39 + warp + lane];

            // a pairs: even-aligned components of LDS.128 results (free packs)
            ull pa[4];
            pa[0] = pack2(a0.x, a0.y);
            pa[1] = pack2(a0.z, a0.w);
            pa[2] = pack2(a1.x, a1.y);
            pa[3] = pack2(a1.z, a1.w);

            float bw[16] = {b0.x, b0.y, b0.z, b0.w,
                            b1.x, b1.y, b1.z, b1.w,
                            b2.x, b2.y, b2.z, b2.w,
                            b3.x, b3.y, b3.z, b3.w};
            // even-start pairs (aligned, free) and odd-start pairs (7 packs)
            ull pe[8], po[7];
#pragma unroll
            for (int k = 0; k < 8; ++k) pe[k] = pack2(bw[2 * k], bw[2 * k + 1]);
#pragma unroll
            for (int k = 0; k < 7; ++k) po[k] = pack2(bw[2 * k + 1], bw[2 * k + 2]);

#pragma unroll
            for (int i = 0; i < 8; ++i)
#pragma unroll
                for (int jp = 0; jp < 4; ++jp) {
                    int s = i + 2 * jp;          // b window start index
                    ull bp2 = (s & 1) ? po[s >> 1] : pe[s >> 1];
                    fma2(acc2[i][jp], pa[jp], bp2);
                }
        }
    }

    // store: unpack pairs, 2 float4 per valid ctr, coalesced across lanes
    const int w0 = lane * 8;
#pragma unroll
    for (int i = 0; i < 8; ++i) {
        int ctr = warp * 8 + i;
        if (ctr < NCTR) {
            float v[8];
#pragma unroll
            for (int jp = 0; jp < 4; ++jp)
                unpack2(acc2[i][jp], v[2 * jp], v[2 * jp + 1]);
            float* dst = O + (((size_t)bi * NCTR + ctr) * H_DIM + h) * W_DIM + w0;
            ((float4*)dst)[0] = make_float4(v[0], v[1], v[2], v[3]);
            ((float4*)dst)[1] = make_float4(v[4], v[5], v[6], v[7]);
        }
    }
}

extern "C" void kernel_launch(void* const* d_in, const int* in_sizes, int n_in,
                              void* d_out, int out_size)
{
    const float* a = (const float*)d_in[0];
    const float* b = (const float*)d_in[1];
    float* out = (float*)d_out;

    dim3 grid(B_DIM * H_DIM);
    dim3 block(NT);
    corr_kernel<<<grid, block>>>(a, b, out);
}

// round 4
// speedup vs baseline: 2.4861x; 1.6754x over previous
#include <cuda_runtime.h>
#include <cstdint>

// Horizontal correlation cost volume via banded tf32 mma.sync GEMM.
// a,b: fp32 [B=8, C=128, H=192, W=256], D=40.
// out[bi, ctr, h, w] = sum_c a[bi,c,h,w] * bp[bi,c,h, ctr+w], bp left-padded by 40.
//
// Per CTA: one (bi,h) row. 512 threads = 16 warps; warp = one 16-wide w tile.
// out[w, ctr] = D[w, w+ctr] where D = A'^T B' (K=128 channels); each warp
// computes only the 7 n-tiles of 8 its diagonal band touches (waste 56/41).
// m16n8k8 tf32 mma.sync, operands rounded with cvt.rna.tf32.f32.
// Channels stream through a 2-stage cp.async pipeline (8 ch = 1 K-step/chunk).
// Epilogue: band-extract into a 41x260 smem tile (conflict-free STS), then
// fully coalesced float4 stores.

#define C_TOT   128
#define W_DIM   256
#define H_DIM   192
#define B_DIM   8
#define NCTR    41
#define NT      512
#define CC      8                  // channels per chunk = K per mma step
#define NCHUNK  (C_TOT / CC)       // 16

#define A_PITCH 264                // 256 data + 8 pad (8-bank shift per row)
#define B_PITCH 312                // 304 data (40 zero|256|8 zero) + 8 pad
#define STAGE_F (CC * (A_PITCH + B_PITCH))   // 4608 floats per stage
#define B_OFF   (CC * A_PITCH)               // 2112 floats
#define OUT_PITCH 260
#define SMEM_FLOATS (NCTR * OUT_PITCH)       // 10660 > 2*STAGE_F = 9216

__device__ __forceinline__ void cpasync16(uint32_t dst, const void* src) {
    asm volatile("cp.async.cg.shared.global [%0], [%1], 16;\n" :: "r"(dst), "l"(src));
}
__device__ __forceinline__ void cp_commit() {
    asm volatile("cp.async.commit_group;\n");
}
__device__ __forceinline__ void cp_wait0() {
    asm volatile("cp.async.wait_group 0;\n" ::: "memory");
}
__device__ __forceinline__ uint32_t to_tf32(float f) {
    uint32_t u;
    asm("cvt.rna.tf32.f32 %0, %1;" : "=r"(u) : "f"(f));
    return u;
}
__device__ __forceinline__ void mma_tf32(float& d0, float& d1, float& d2, float& d3,
                                         uint32_t a0, uint32_t a1, uint32_t a2, uint32_t a3,
                                         uint32_t b0, uint32_t b1) {
    asm volatile("mma.sync.aligned.m16n8k8.row.col.f32.tf32.tf32.f32 "
                 "{%0,%1,%2,%3}, {%4,%5,%6,%7}, {%8,%9}, {%0,%1,%2,%3};\n"
                 : "+f"(d0), "+f"(d1), "+f"(d2), "+f"(d3)
                 : "r"(a0), "r"(a1), "r"(a2), "r"(a3), "r"(b0), "r"(b1));
}

__global__ __launch_bounds__(NT, 2)
void corr_kernel(const float* __restrict__ A,
                 const float* __restrict__ B,
                 float* __restrict__ O)
{
    __shared__ __align__(16) float sm[SMEM_FLOATS];

    const int row  = blockIdx.x;
    const int bi   = row / H_DIM;
    const int h    = row - bi * H_DIM;
    const int tid  = threadIdx.x;
    const int wid  = tid >> 5;                 // 0..15 -> w tile base
    const int lane = tid & 31;
    const int WB   = wid * 16;
    const int q    = lane & 3;                 // k-in-group / col group
    const int r0   = lane >> 2;                // row-in-group

    const size_t plane = (size_t)H_DIM * W_DIM;
    const float* Arow = A + ((size_t)bi * C_TOT * H_DIM + h) * W_DIM;
    const float* Brow = B + ((size_t)bi * C_TOT * H_DIM + h) * W_DIM;

    const uint32_t smb = (uint32_t)__cvta_generic_to_shared(sm);

    // ---- zero the permanent pad blocks of b rows (never overwritten) ----
    // b row floats: [0..39]=0, [40..295]=data, [296..303]=0 -> float4 blocks {0..9,74,75}
    if (tid < 2 * CC * 12) {
        int st = tid / (CC * 12);
        int t  = tid - st * (CC * 12);
        int c  = t / 12;
        int j  = t - c * 12;
        int blk = (j < 10) ? j : (64 + j);     // 74, 75
        float4* p = (float4*)(sm + st * STAGE_F + B_OFF + c * B_PITCH) + blk;
        *p = make_float4(0.f, 0.f, 0.f, 0.f);
    }

    float acc[7][4];
#pragma unroll
    for (int jt = 0; jt < 7; ++jt)
#pragma unroll
        for (int k = 0; k < 4; ++k)
            acc[jt][k] = 0.0f;

    // ---- prefetch chunk ch into stage st (each thread: 2 cp.async.16B) ----
    auto prefetch = [&](int ch, int st) {
        {   // a: 512 blocks, one per thread
            int c = tid >> 6, blk = tid & 63;
            uint32_t dst = smb + (st * STAGE_F + c * A_PITCH) * 4 + blk * 16;
            cpasync16(dst, Arow + (size_t)(ch * CC + c) * plane + blk * 4);
        }
        {   // b: 512 data blocks, one per thread
            int c = tid >> 6, g = tid & 63;
            uint32_t dst = smb + (st * STAGE_F + B_OFF + c * B_PITCH) * 4 + (g + 10) * 16;
            cpasync16(dst, Brow + (size_t)(ch * CC + c) * plane + g * 4);
        }
        cp_commit();
    };

    prefetch(0, 0);

    for (int ch = 0; ch < NCHUNK; ++ch) {
        const int st = ch & 1;
        cp_wait0();
        __syncthreads();

        if (ch + 1 < NCHUNK)
            prefetch(ch + 1, st ^ 1);          // overlaps compute below

        const float* as = sm + st * STAGE_F;
        const float* bs = sm + st * STAGE_F + B_OFF;

        // A fragment (m16 x k8, row-major): a0=(r0,q) a1=(r0+8,q) a2=(r0,q+4) a3=(r0+8,q+4)
        uint32_t a0 = to_tf32(as[q * A_PITCH + WB + r0]);
        uint32_t a1 = to_tf32(as[q * A_PITCH + WB + r0 + 8]);
        uint32_t a2 = to_tf32(as[(q + 4) * A_PITCH + WB + r0]);
        uint32_t a3 = to_tf32(as[(q + 4) * A_PITCH + WB + r0 + 8]);

#pragma unroll
        for (int jt = 0; jt < 7; ++jt) {
            // B fragment (k8 x n8, col-major): b0=(k=q, n=r0), b1=(k=q+4, n=r0)
            int j = WB + jt * 8 + r0;          // bp float index within row
            uint32_t b0 = to_tf32(bs[q * B_PITCH + j]);
            uint32_t b1 = to_tf32(bs[(q + 4) * B_PITCH + j]);
            mma_tf32(acc[jt][0], acc[jt][1], acc[jt][2], acc[jt][3],
                     a0, a1, a2, a3, b0, b1);
        }
    }

    // ---- band extraction into smem: out_s[ctr][w] (reuses pipeline smem) ----
    __syncthreads();
#pragma unroll
    for (int jt = 0; jt < 7; ++jt) {
        int nb = jt * 8 + 2 * q;               // n for regs 0/1
        // c0: (row r0,   col nb)   c1: (r0,   nb+1)
        // c2: (row r0+8, col nb)   c3: (r0+8, nb+1)
        int ctr00 = nb - r0;
        int ctr10 = nb - (r0 + 8);
        if (ctr00 >= 0 && ctr00 <= 40)       sm[ctr00 * OUT_PITCH + WB + r0]          = acc[jt][0];
        if (ctr00 + 1 >= 0 && ctr00 + 1 <= 40) sm[(ctr00 + 1) * OUT_PITCH + WB + r0]   = acc[jt][1];
        if (ctr10 >= 0 && ctr10 <= 40)       sm[ctr10 * OUT_PITCH + WB + r0 + 8]      = acc[jt][2];
        if (ctr10 + 1 >= 0 && ctr10 + 1 <= 40) sm[(ctr10 + 1) * OUT_PITCH + WB + r0 + 8] = acc[jt][3];
    }
    __syncthreads();

    // ---- coalesced write-out: 41 x 64 float4 ----
    for (int idx = tid; idx < NCTR * 64; idx += NT) {
        int ctr = idx >> 6;
        int blk = idx & 63;
        float4 v = *(const float4*)(sm + ctr * OUT_PITCH + blk * 4);
        float* dst = O + (((size_t)bi * NCTR + ctr) * H_DIM + h) * W_DIM + blk * 4;
        *(float4*)dst = v;
    }
}

extern "C" void kernel_launch(void* const* d_in, const int* in_sizes, int n_in,
                              void* d_out, int out_size)
{
    const float* a = (const float*)d_in[0];
    const float* b = (const float*)d_in[1];
    float* out = (float*)d_out;

    dim3 grid(B_DIM * H_DIM);   // 1536 CTAs, one per (batch, h) row
    dim3 block(NT);
    corr_kernel<<<grid, block>>>(a, b, out);
}

// round 5
// speedup vs baseline: 3.4063x; 1.3701x over previous
#include <cuda_runtime.h>
#include <cstdint>

// Horizontal correlation cost volume via banded tf32 mma.sync GEMM.
// a,b: fp32 [B=8, C=128, H=192, W=256], D=40.
// out[bi, ctr, h, w] = sum_c a[bi,c,h,w] * bp[bi,c,h, ctr+w], bp left-padded by 40.
//
// Per CTA: one (bi,h) row. 512 threads = 16 warps; warp = one 16-wide w tile.
// out[w, ctr] = D[w, w+ctr] where D = A'^T B' (K=128); each warp computes only
// the 7 n-tiles of 8 its diagonal band touches. m16n8k8 tf32 mma.sync with
// cvt.rna.tf32.f32 operands.
//
// Channels stream through a 4-stage cp.async ring (prefetch distance 3,
// wait_group 2, empty commit_group at the tail to keep the FIFO invariant):
// 3 x 16KB chunks in flight per CTA -> ~14MB chip-wide outstanding, enough to
// saturate HBM per Little's law (2-stage version measured 54% = outstanding-
// bytes-limited, matching the 4.7MB it kept in flight).
//
// Epilogue: band-extract into a 41x260 smem tile (reuses ring smem), then
// fully coalesced float4 stores.

#define C_TOT   128
#define W_DIM   256
#define H_DIM   192
#define B_DIM   8
#define NCTR    41
#define NT      512
#define CC      8                  // channels per chunk = K per mma step
#define NCHUNK  (C_TOT / CC)       // 16
#define NSTAGE  4

#define A_PITCH 264                // 256 data + 8 pad (8-bank shift per row)
#define B_PITCH 312                // 304 data (40 zero|256|8 zero) + 8 pad
#define STAGE_F (CC * (A_PITCH + B_PITCH))   // 4608 floats per stage
#define B_OFF   (CC * A_PITCH)               // 2112 floats
#define OUT_PITCH 260
#define OUT_F   (NCTR * OUT_PITCH)           // 10660 floats
#define RING_F  (NSTAGE * STAGE_F)           // 18432 floats
#define SMEM_BYTES (RING_F * 4)              // 73728 B  (> OUT_F*4 = 42640)

__device__ __forceinline__ void cpasync16(uint32_t dst, const void* src) {
    asm volatile("cp.async.cg.shared.global [%0], [%1], 16;\n" :: "r"(dst), "l"(src));
}
__device__ __forceinline__ void cp_commit() {
    asm volatile("cp.async.commit_group;\n");
}
__device__ __forceinline__ void cp_wait2() {
    asm volatile("cp.async.wait_group 2;\n" ::: "memory");
}
__device__ __forceinline__ uint32_t to_tf32(float f) {
    uint32_t u;
    asm("cvt.rna.tf32.f32 %0, %1;" : "=r"(u) : "f"(f));
    return u;
}
__device__ __forceinline__ void mma_tf32(float& d0, float& d1, float& d2, float& d3,
                                         uint32_t a0, uint32_t a1, uint32_t a2, uint32_t a3,
                                         uint32_t b0, uint32_t b1) {
    asm volatile("mma.sync.aligned.m16n8k8.row.col.f32.tf32.tf32.f32 "
                 "{%0,%1,%2,%3}, {%4,%5,%6,%7}, {%8,%9}, {%0,%1,%2,%3};\n"
                 : "+f"(d0), "+f"(d1), "+f"(d2), "+f"(d3)
                 : "r"(a0), "r"(a1), "r"(a2), "r"(a3), "r"(b0), "r"(b1));
}

__global__ __launch_bounds__(NT, 2)
void corr_kernel(const float* __restrict__ A,
                 const float* __restrict__ B,
                 float* __restrict__ O)
{
    extern __shared__ __align__(16) float sm[];

    const int row  = blockIdx.x;
    const int bi   = row / H_DIM;
    const int h    = row - bi * H_DIM;
    const int tid  = threadIdx.x;
    const int wid  = tid >> 5;
    const int lane = tid & 31;
    const int WB   = wid * 16;
    const int q    = lane & 3;
    const int r0   = lane >> 2;

    const size_t plane = (size_t)H_DIM * W_DIM;
    const float* Arow = A + ((size_t)bi * C_TOT * H_DIM + h) * W_DIM;
    const float* Brow = B + ((size_t)bi * C_TOT * H_DIM + h) * W_DIM;

    const uint32_t smb = (uint32_t)__cvta_generic_to_shared(sm);

    // ---- zero the permanent pad blocks of b rows in every stage (once) ----
    // b row float4 blocks {0..9, 74, 75} are pad; cp.async never writes them.
    if (tid < NSTAGE * CC * 12) {
        int st = tid / (CC * 12);
        int t  = tid - st * (CC * 12);
        int c  = t / 12;
        int j  = t - c * 12;
        int blk = (j < 10) ? j : (64 + j);     // 74, 75
        float4* p = (float4*)(sm + st * STAGE_F + B_OFF + c * B_PITCH) + blk;
        *p = make_float4(0.f, 0.f, 0.f, 0.f);
    }

    float acc[7][4];
#pragma unroll
    for (int jt = 0; jt < 7; ++jt)
#pragma unroll
        for (int k = 0; k < 4; ++k)
            acc[jt][k] = 0.0f;

    // ---- prefetch chunk ch into stage st (each thread: 2 cp.async.16B) ----
    auto prefetch = [&](int ch, int st) {
        {   // a: 512 blocks, one per thread
            int c = tid >> 6, blk = tid & 63;
            uint32_t dst = smb + (st * STAGE_F + c * A_PITCH) * 4 + blk * 16;
            cpasync16(dst, Arow + (size_t)(ch * CC + c) * plane + blk * 4);
        }
        {   // b: 512 data blocks, one per thread
            int c = tid >> 6, g = tid & 63;
            uint32_t dst = smb + (st * STAGE_F + B_OFF + c * B_PITCH) * 4 + (g + 10) * 16;
            cpasync16(dst, Brow + (size_t)(ch * CC + c) * plane + g * 4);
        }
        cp_commit();
    };

    prefetch(0, 0);
    prefetch(1, 1);
    prefetch(2, 2);

    for (int ch = 0; ch < NCHUNK; ++ch) {
        const int st = ch & (NSTAGE - 1);
        cp_wait2();            // groups ch+1, ch+2 may remain -> chunk ch done
        __syncthreads();       // all threads done computing chunk ch-1

        if (ch + 3 < NCHUNK) prefetch(ch + 3, (ch + 3) & (NSTAGE - 1));
        else                 cp_commit();     // empty group keeps FIFO invariant

        const float* as = sm + st * STAGE_F;
        const float* bs = sm + st * STAGE_F + B_OFF;

        // A fragment (m16 x k8, row-major)
        uint32_t a0 = to_tf32(as[q * A_PITCH + WB + r0]);
        uint32_t a1 = to_tf32(as[q * A_PITCH + WB + r0 + 8]);
        uint32_t a2 = to_tf32(as[(q + 4) * A_PITCH + WB + r0]);
        uint32_t a3 = to_tf32(as[(q + 4) * A_PITCH + WB + r0 + 8]);

#pragma unroll
        for (int jt = 0; jt < 7; ++jt) {
            int j = WB + jt * 8 + r0;          // bp float index within row
            uint32_t b0 = to_tf32(bs[q * B_PITCH + j]);
            uint32_t b1 = to_tf32(bs[(q + 4) * B_PITCH + j]);
            mma_tf32(acc[jt][0], acc[jt][1], acc[jt][2], acc[jt][3],
                     a0, a1, a2, a3, b0, b1);
        }
    }

    // ---- band extraction into smem: out_s[ctr][w] (reuses ring smem) ----
    __syncthreads();
#pragma unroll
    for (int jt = 0; jt < 7; ++jt) {
        int nb = jt * 8 + 2 * q;
        int ctr00 = nb - r0;
        int ctr10 = nb - (r0 + 8);
        if (ctr00 >= 0 && ctr00 <= 40)         sm[ctr00 * OUT_PITCH + WB + r0]           = acc[jt][0];
        if (ctr00 + 1 >= 0 && ctr00 + 1 <= 40) sm[(ctr00 + 1) * OUT_PITCH + WB + r0]     = acc[jt][1];
        if (ctr10 >= 0 && ctr10 <= 40)         sm[ctr10 * OUT_PITCH + WB + r0 + 8]       = acc[jt][2];
        if (ctr10 + 1 >= 0 && ctr10 + 1 <= 40) sm[(ctr10 + 1) * OUT_PITCH + WB + r0 + 8] = acc[jt][3];
    }
    __syncthreads();

    // ---- coalesced write-out: 41 x 64 float4 ----
    for (int idx = tid; idx < NCTR * 64; idx += NT) {
        int ctr = idx >> 6;
        int blk = idx & 63;
        float4 v = *(const float4*)(sm + ctr * OUT_PITCH + blk * 4);
        float* dst = O + (((size_t)bi * NCTR + ctr) * H_DIM + h) * W_DIM + blk * 4;
        *(float4*)dst = v;
    }
}

extern "C" void kernel_launch(void* const* d_in, const int* in_sizes, int n_in,
                              void* d_out, int out_size)
{
    const float* a = (const float*)d_in[0];
    const float* b = (const float*)d_in[1];
    float* out = (float*)d_out;

    cudaFuncSetAttribute(corr_kernel,
                         cudaFuncAttributeMaxDynamicSharedMemorySize, SMEM_BYTES);

    dim3 grid(B_DIM * H_DIM);   // 1536 CTAs, one per (batch, h) row
    dim3 block(NT);
    corr_kernel<<<grid, block, SMEM_BYTES>>>(a, b, out);
}

// round 6
// speedup vs baseline: 3.4846x; 1.0230x over previous
#include <cuda_runtime.h>
#include <cstdint>

// Horizontal correlation cost volume via banded tf32 mma.sync GEMM.
// a,b: fp32 [B=8, C=128, H=192, W=256], D=40.
// out[bi, ctr, h, w] = sum_c a[bi,c,h,w] * bp[bi,c,h, ctr+w], bp left-padded by 40.
//
// Per CTA: one (bi,h) row. 512 threads = 16 warps; warp = one 16-wide w tile.
// out[w, ctr] = D[w, w+ctr] where D = A'^T B' (K=128); each warp computes only
// the 7 n-tiles of 8 its diagonal band touches. m16n8k8 tf32 mma.sync with
// cvt.rna.tf32.f32 operands.
//
// Channels stream through a 6-stage cp.async ring (prefetch distance 5,
// wait_group 4, empty commit_group at the tail): 5 x 16KB chunks in flight per
// CTA -> ~24MB chip-wide outstanding. 4-stage version measured DRAM=74.3%;
// deeper ring + more barrier slack targets ~85%.
//
// Epilogue: band-extract into a 41x260 smem tile (reuses ring smem), then
// fully coalesced float4 stores.

#define C_TOT   128
#define W_DIM   256
#define H_DIM   192
#define B_DIM   8
#define NCTR    41
#define NT      512
#define CC      8                  // channels per chunk = K per mma step
#define NCHUNK  (C_TOT / CC)       // 16
#define NSTAGE  6
#define PFD     5                  // prefetch distance

#define A_PITCH 264                // 256 data + 8 pad (8-bank shift per row)
#define B_PITCH 312                // 304 data (40 zero|256|8 zero) + 8 pad
#define STAGE_F (CC * (A_PITCH + B_PITCH))   // 4608 floats per stage
#define B_OFF   (CC * A_PITCH)               // 2112 floats
#define OUT_PITCH 260
#define OUT_F   (NCTR * OUT_PITCH)           // 10660 floats
#define RING_F  (NSTAGE * STAGE_F)           // 27648 floats
#define SMEM_BYTES (RING_F * 4)              // 110592 B (> OUT_F*4 = 42640)

__device__ __forceinline__ void cpasync16(uint32_t dst, const void* src) {
    asm volatile("cp.async.cg.shared.global [%0], [%1], 16;\n" :: "r"(dst), "l"(src));
}
__device__ __forceinline__ void cp_commit() {
    asm volatile("cp.async.commit_group;\n");
}
__device__ __forceinline__ void cp_wait4() {
    asm volatile("cp.async.wait_group 4;\n" ::: "memory");
}
__device__ __forceinline__ uint32_t to_tf32(float f) {
    uint32_t u;
    asm("cvt.rna.tf32.f32 %0, %1;" : "=r"(u) : "f"(f));
    return u;
}
__device__ __forceinline__ void mma_tf32(float& d0, float& d1, float& d2, float& d3,
                                         uint32_t a0, uint32_t a1, uint32_t a2, uint32_t a3,
                                         uint32_t b0, uint32_t b1) {
    asm volatile("mma.sync.aligned.m16n8k8.row.col.f32.tf32.tf32.f32 "
                 "{%0,%1,%2,%3}, {%4,%5,%6,%7}, {%8,%9}, {%0,%1,%2,%3};\n"
                 : "+f"(d0), "+f"(d1), "+f"(d2), "+f"(d3)
                 : "r"(a0), "r"(a1), "r"(a2), "r"(a3), "r"(b0), "r"(b1));
}

__global__ __launch_bounds__(NT, 2)
void corr_kernel(const float* __restrict__ A,
                 const float* __restrict__ B,
                 float* __restrict__ O)
{
    extern __shared__ __align__(16) float sm[];

    const int row  = blockIdx.x;
    const int bi   = row / H_DIM;
    const int h    = row - bi * H_DIM;
    const int tid  = threadIdx.x;
    const int wid  = tid >> 5;
    const int lane = tid & 31;
    const int WB   = wid * 16;
    const int q    = lane & 3;
    const int r0   = lane >> 2;

    const size_t plane = (size_t)H_DIM * W_DIM;
    const float* Arow = A + ((size_t)bi * C_TOT * H_DIM + h) * W_DIM;
    const float* Brow = B + ((size_t)bi * C_TOT * H_DIM + h) * W_DIM;

    const uint32_t smb = (uint32_t)__cvta_generic_to_shared(sm);

    // ---- zero the permanent pad blocks of b rows in every stage (once) ----
    // b row float4 blocks {0..9, 74, 75} are pad; cp.async never writes them.
    for (int t = tid; t < NSTAGE * CC * 12; t += NT) {
        int st = t / (CC * 12);
        int u  = t - st * (CC * 12);
        int c  = u / 12;
        int j  = u - c * 12;
        int blk = (j < 10) ? j : (64 + j);     // 74, 75
        float4* p = (float4*)(sm + st * STAGE_F + B_OFF + c * B_PITCH) + blk;
        *p = make_float4(0.f, 0.f, 0.f, 0.f);
    }

    float acc[7][4];
#pragma unroll
    for (int jt = 0; jt < 7; ++jt)
#pragma unroll
        for (int k = 0; k < 4; ++k)
            acc[jt][k] = 0.0f;

    // per-thread fixed load coordinates
    const int pc   = tid >> 6;                 // channel within chunk (0..7)
    const int pblk = tid & 63;                 // float4 block (0..63)
    const float* Asrc0 = Arow + (size_t)pc * plane + pblk * 4;
    const float* Bsrc0 = Brow + (size_t)pc * plane + pblk * 4;
    const uint32_t adst0 = smb + (pc * A_PITCH) * 4 + pblk * 16;
    const uint32_t bdst0 = smb + (B_OFF + pc * B_PITCH) * 4 + (pblk + 10) * 16;
    const size_t chstep = (size_t)CC * plane;

    auto prefetch = [&](int ch, int st) {
        const size_t off = (size_t)ch * chstep;
        const uint32_t so = (uint32_t)(st * STAGE_F * 4);
        cpasync16(adst0 + so, Asrc0 + off);
        cpasync16(bdst0 + so, Bsrc0 + off);
        cp_commit();
    };

#pragma unroll
    for (int p = 0; p < PFD; ++p)
        prefetch(p, p);

    for (int ch = 0; ch < NCHUNK; ++ch) {
        const int st = ch % NSTAGE;
        cp_wait4();            // 4 newest groups may remain -> chunk ch resident
        __syncthreads();       // all threads done computing chunk ch-1

        if (ch + PFD < NCHUNK) prefetch(ch + PFD, (ch + PFD) % NSTAGE);
        else                   cp_commit();   // empty group keeps FIFO invariant

        const float* as = sm + st * STAGE_F;
        const float* bs = sm + st * STAGE_F + B_OFF;

        // A fragment (m16 x k8, row-major)
        uint32_t a0 = to_tf32(as[q * A_PITCH + WB + r0]);
        uint32_t a1 = to_tf32(as[q * A_PITCH + WB + r0 + 8]);
        uint32_t a2 = to_tf32(as[(q + 4) * A_PITCH + WB + r0]);
        uint32_t a3 = to_tf32(as[(q + 4) * A_PITCH + WB + r0 + 8]);

#pragma unroll
        for (int jt = 0; jt < 7; ++jt) {
            int j = WB + jt * 8 + r0;          // bp float index within row
            uint32_t b0 = to_tf32(bs[q * B_PITCH + j]);
            uint32_t b1 = to_tf32(bs[(q + 4) * B_PITCH + j]);
            mma_tf32(acc[jt][0], acc[jt][1], acc[jt][2], acc[jt][3],
                     a0, a1, a2, a3, b0, b1);
        }
    }

    // ---- band extraction into smem: out_s[ctr][w] (reuses ring smem) ----
    __syncthreads();
#pragma unroll
    for (int jt = 0; jt < 7; ++jt) {
        int nb = jt * 8 + 2 * q;
        int ctr00 = nb - r0;
        int ctr10 = nb - (r0 + 8);
        if (ctr00 >= 0 && ctr00 <= 40)         sm[ctr00 * OUT_PITCH + WB + r0]           = acc[jt][0];
        if (ctr00 + 1 >= 0 && ctr00 + 1 <= 40) sm[(ctr00 + 1) * OUT_PITCH + WB + r0]     = acc[jt][1];
        if (ctr10 >= 0 && ctr10 <= 40)         sm[ctr10 * OUT_PITCH + WB + r0 + 8]       = acc[jt][2];
        if (ctr10 + 1 >= 0 && ctr10 + 1 <= 40) sm[(ctr10 + 1) * OUT_PITCH + WB + r0 + 8] = acc[jt][3];
    }
    __syncthreads();

    // ---- coalesced write-out: 41 x 64 float4 ----
    for (int idx = tid; idx < NCTR * 64; idx += NT) {
        int ctr = idx >> 6;
        int blk = idx & 63;
        float4 v = *(const float4*)(sm + ctr * OUT_PITCH + blk * 4);
        float* dst = O + (((size_t)bi * NCTR + ctr) * H_DIM + h) * W_DIM + blk * 4;
        *(float4*)dst = v;
    }
}

extern "C" void kernel_launch(void* const* d_in, const int* in_sizes, int n_in,
                              void* d_out, int out_size)
{
    const float* a = (const float*)d_in[0];
    const float* b = (const float*)d_in[1];
    float* out = (float*)d_out;

    cudaFuncSetAttribute(corr_kernel,
                         cudaFuncAttributeMaxDynamicSharedMemorySize, SMEM_BYTES);

    dim3 grid(B_DIM * H_DIM);   // 1536 CTAs, one per (batch, h) row
    dim3 block(NT);
    corr_kernel<<<grid, block, SMEM_BYTES>>>(a, b, out);
}